// round 11
// baseline (speedup 1.0000x reference)
#include <cuda_runtime.h>
#include <cuda_fp16.h>
#include <math.h>

#define BATCH 2
#define SEQ   2048
#define DMODEL 512
#define NHEADS 8
#define DHEAD 64
#define INNER 512
#define QKV3  1536
#define MROWS (BATCH*SEQ)   // 4096

// Scratch (device globals; allocation is forbidden)
__device__ __half g_qk[MROWS * 1024];            // q at [r][0..511], k at [r][512..1023]
__device__ __half g_vT[BATCH * NHEADS * DHEAD * SEQ]; // [(b*8+h)*64+d][s]
__device__ __half g_attn[MROWS * INNER];         // attention out, fp16
__device__ __half g_xh[MROWS * DMODEL];
__device__ __half g_wqh[QKV3 * DMODEL];
__device__ __half g_woh[DMODEL * INNER];
__device__ float g_t[2048];
__device__ float g_part[32];
__device__ float g_scales[2];
__device__ float g_k2q;                          // exp(temperature)*log2(e)
__device__ unsigned g_ctr = 0;                   // sn_finish completion counter

// ---------------------------------------------------------------------------
// helpers
// ---------------------------------------------------------------------------
__device__ __forceinline__ float ex2f(float x) {
    float r;
    asm("ex2.approx.ftz.f32 %0, %1;" : "=f"(r) : "f"(x));
    return r;
}

__device__ __forceinline__ void mma16(float* c, const unsigned* a, const unsigned* b) {
    asm volatile(
        "mma.sync.aligned.m16n8k16.row.col.f32.f16.f16.f32 "
        "{%0,%1,%2,%3}, {%4,%5,%6,%7}, {%8,%9}, {%0,%1,%2,%3};"
        : "+f"(c[0]), "+f"(c[1]), "+f"(c[2]), "+f"(c[3])
        : "r"(a[0]), "r"(a[1]), "r"(a[2]), "r"(a[3]), "r"(b[0]), "r"(b[1]));
}

__device__ __forceinline__ void ldsm4(unsigned& r0, unsigned& r1,
                                      unsigned& r2, unsigned& r3, unsigned a) {
    asm volatile("ldmatrix.sync.aligned.m8n8.x4.shared.b16 {%0,%1,%2,%3}, [%4];"
                 : "=r"(r0), "=r"(r1), "=r"(r2), "=r"(r3) : "r"(a));
}

__device__ __forceinline__ void cpa16(unsigned dst, const void* src) {
    asm volatile("cp.async.cg.shared.global [%0], [%1], 16;" :: "r"(dst), "l"(src));
}
#define CP_COMMIT() asm volatile("cp.async.commit_group;")
#define CP_WAIT0()  asm volatile("cp.async.wait_group 0;")
#define CP_WAIT1()  asm volatile("cp.async.wait_group 1;")

// ---------------------------------------------------------------------------
// prep: fused fp16 conversion (x, W_qkv, W_out) + spectral-norm row dots
// ---------------------------------------------------------------------------
#define C0 (MROWS * DMODEL / 8)
#define C1 (QKV3 * DMODEL / 8)
#define C2 (DMODEL * INNER / 8)
#define NB_CVT ((C0 + C1 + C2) / 256)
__global__ __launch_bounds__(256)
void prep(const float* __restrict__ x, const float* __restrict__ wq,
          const float* __restrict__ wo, const float* __restrict__ uq,
          const float* __restrict__ uo)
{
    const int bid = blockIdx.x;
    const int tid = threadIdx.x;
    if (bid < NB_CVT) {
        int i = bid * 256 + tid;
        const float* src; __half* dst; int off;
        if (i < C0)           { src = x;  dst = g_xh;  off = i; }
        else if (i < C0 + C1) { src = wq; dst = g_wqh; off = i - C0; }
        else                  { src = wo; dst = g_woh; off = i - C0 - C1; }
        float4 a = ((const float4*)src)[(size_t)off * 2];
        float4 b = ((const float4*)src)[(size_t)off * 2 + 1];
        __half2 h0 = __floats2half2_rn(a.x, a.y);
        __half2 h1 = __floats2half2_rn(a.z, a.w);
        __half2 h2 = __floats2half2_rn(b.x, b.y);
        __half2 h3 = __floats2half2_rn(b.z, b.w);
        uint4 u = make_uint4(*(unsigned*)&h0, *(unsigned*)&h1,
                             *(unsigned*)&h2, *(unsigned*)&h3);
        *(uint4*)(dst + (size_t)off * 8) = u;
    } else {
        int rb = bid - NB_CVT;
        const float* W; const float* u; int row;
        if (rb < 1536) { W = wq; u = uq; row = rb; }
        else           { W = wo; u = uo; row = rb - 1536; }
        const float* wr = W + (size_t)row * 512;
        float s = wr[tid] * u[tid] + wr[tid + 256] * u[tid + 256];
        #pragma unroll
        for (int o = 16; o >= 1; o >>= 1) s += __shfl_xor_sync(0xffffffffu, s, o);
        __shared__ float red[8];
        if ((tid & 31) == 0) red[tid >> 5] = s;
        __syncthreads();
        if (tid == 0) {
            float tot = 0.f;
            #pragma unroll
            for (int q = 0; q < 8; ++q) tot += red[q];
            g_t[rb] = tot;
        }
    }
}

// ---------------------------------------------------------------------------
// sn_finish: coldot partials (32 blocks); last block computes both scales.
// ---------------------------------------------------------------------------
__global__ __launch_bounds__(256)
void sn_finish(const float* __restrict__ Wq, const float* __restrict__ Wo,
               const float* __restrict__ sq, const float* __restrict__ so,
               const float* __restrict__ temp)
{
    const int blk = blockIdx.x;
    const int tid = threadIdx.x;
    {
        int w = blk >> 4;
        int cblk = blk & 15;
        const float* W = w ? Wo : Wq;
        int R = w ? 512 : 1536;
        int toff = w ? 1536 : 0;
        int dl = tid & 31;
        int rg = tid >> 5;
        int d = cblk * 32 + dl;
        float s = 0.f;
        for (int r = rg; r < R; r += 8) s += W[(size_t)r * 512 + d] * g_t[toff + r];
        __shared__ float red[8][33];
        red[rg][dl] = s;
        __syncthreads();
        if (rg == 0) {
            float cs = 0.f;
            #pragma unroll
            for (int q = 0; q < 8; ++q) cs += red[q][dl];
            cs = cs * cs;
            #pragma unroll
            for (int o = 16; o >= 1; o >>= 1) cs += __shfl_xor_sync(0xffffffffu, cs, o);
            if (dl == 0) g_part[blk] = cs;
        }
    }
    // last-block pattern
    __threadfence();
    __syncthreads();
    __shared__ unsigned last;
    if (tid == 0) last = atomicAdd(&g_ctr, 1u);
    __syncthreads();
    if (last != 31) return;
    __threadfence();   // acquire: all g_part visible

    const int w  = tid >> 7;        // 0 or 1
    const int tl = tid & 127;
    float ssq = (tl < 16) ? g_part[w * 16 + tl] : 0.f;
    const int R = w ? 512 : 1536;
    const int off = w ? 1536 : 0;
    float tt = 0.f;
    for (int r = tl; r < R; r += 128) { float v = g_t[off + r]; tt += v * v; }
    __shared__ float ra[256], rb[256];
    ra[tid] = ssq; rb[tid] = tt;
    __syncthreads();
    for (int sft = 64; sft >= 1; sft >>= 1) {
        if (tl < sft) { ra[tid] += ra[tid + sft]; rb[tid] += rb[tid + sft]; }
        __syncthreads();
    }
    if (tl == 0) {
        float sigma_w = sqrtf(ra[w * 128] / rb[w * 128]);
        g_scales[w] = (w ? so[0] : sq[0]) / sigma_w;
        if (w == 0) {
            g_k2q = expf(temp[0]) * 1.4426950408889634f;
            g_ctr = 0;   // reset for next graph replay
        }
    }
}

// ---------------------------------------------------------------------------
// fp16 GEMM with ldmatrix fragment loads (round-10 validated).
// ---------------------------------------------------------------------------
#define GST (128 * 36)
__global__ __launch_bounds__(256, 2)
void gemm_h(const __half* __restrict__ A, const __half* __restrict__ B,
            float* __restrict__ C, int M, int N, int K,
            int mode, const float* __restrict__ bias)
{
    extern __shared__ unsigned smg[];
    const int t    = threadIdx.x;
    const int lane = t & 31;
    const int wid  = t >> 5;
    const int g  = lane >> 2;
    const int tg = lane & 3;
    const int wm = (wid >> 2) * 64;
    const int wn = (wid & 3) * 32;
    const int row0 = blockIdx.y * 128;
    const int col0 = blockIdx.x * 128;
    const int NK = K >> 6;

    const unsigned sb = (unsigned)__cvta_generic_to_shared(smg);
    const int crow = t >> 3;
    const int cch  = (t & 7) * 8;

    const int arow  = (lane & 7) + ((lane >> 3) & 1) * 8;
    const int acol4 = ((lane >> 4) & 1) * 4;
    const int brow  = (lane & 7) + ((lane >> 4) & 1) * 8;
    const int bcol4 = ((lane >> 3) & 1) * 4;

    auto issue = [&](int st, int k0) {
        unsigned so = sb + (unsigned)(st * 2 * GST) * 4u;
        #pragma unroll
        for (int i = 0; i < 4; ++i) {
            int row = crow + i * 32;
            cpa16(so + (unsigned)(row * 36 + (t & 7) * 4) * 4u,
                  A + (size_t)(row0 + row) * K + k0 + cch);
            cpa16(so + (unsigned)(GST + row * 36 + (t & 7) * 4) * 4u,
                  B + (size_t)(col0 + row) * K + k0 + cch);
        }
    };

    issue(0, 0);  CP_COMMIT();
    issue(1, 64); CP_COMMIT();

    float acc[4][4][4];
    #pragma unroll
    for (int mi = 0; mi < 4; ++mi)
        #pragma unroll
        for (int ni = 0; ni < 4; ++ni)
            #pragma unroll
            for (int r = 0; r < 4; ++r) acc[mi][ni][r] = 0.f;

    for (int ks = 0; ks < NK; ++ks) {
        if (ks + 1 < NK) CP_WAIT1(); else CP_WAIT0();
        __syncthreads();
        if (ks + 2 < NK) { issue((ks + 2) % 3, (ks + 2) * 64); CP_COMMIT(); }

        const unsigned sA = sb + (unsigned)((ks % 3) * 2 * GST) * 4u;
        const unsigned sB = sA + (unsigned)GST * 4u;
        #pragma unroll
        for (int ki = 0; ki < 4; ++ki) {
            const int kk = ki * 8;
            unsigned af[4][4], bf[4][2];
            #pragma unroll
            for (int mi = 0; mi < 4; ++mi)
                ldsm4(af[mi][0], af[mi][1], af[mi][2], af[mi][3],
                      sA + (unsigned)((wm + mi * 16 + arow) * 36 + kk + acol4) * 4u);
            #pragma unroll
            for (int p = 0; p < 2; ++p)
                ldsm4(bf[p * 2][0], bf[p * 2][1], bf[p * 2 + 1][0], bf[p * 2 + 1][1],
                      sB + (unsigned)((wn + p * 16 + brow) * 36 + kk + bcol4) * 4u);
            #pragma unroll
            for (int mi = 0; mi < 4; ++mi)
                #pragma unroll
                for (int ni = 0; ni < 4; ++ni)
                    mma16(acc[mi][ni], af[mi], bf[ni]);
        }
    }

    if (mode == 0) {
        float scale = g_scales[0];
        if (col0 < 512) scale *= g_k2q;
        const bool is_v = (col0 >= 1024);
        #pragma unroll
        for (int mi = 0; mi < 4; ++mi) {
            int r = row0 + wm + mi * 16 + g;
            #pragma unroll
            for (int ni = 0; ni < 4; ++ni) {
                int c = col0 + wn + ni * 8 + tg * 2;
                float v0 = acc[mi][ni][0] * scale;
                float v1 = acc[mi][ni][1] * scale;
                float v2 = acc[mi][ni][2] * scale;
                float v3 = acc[mi][ni][3] * scale;
                if (!is_v) {
                    __half2 lo = __floats2half2_rn(v0, v1);
                    __half2 hi = __floats2half2_rn(v2, v3);
                    *(__half2*)&g_qk[(size_t)r * 1024 + c]       = lo;
                    *(__half2*)&g_qk[(size_t)(r + 8) * 1024 + c] = hi;
                } else {
                    int cd = c - 1024;
                    int h  = cd >> 6;
                    int d  = cd & 63;
                    int b  = r >> 11;
                    int s  = r & 2047;
                    size_t base = ((size_t)(b * 8 + h) * 64 + d) * 2048;
                    g_vT[base + s]            = __float2half_rn(v0);
                    g_vT[base + 2048 + s]     = __float2half_rn(v1);
                    g_vT[base + s + 8]        = __float2half_rn(v2);
                    g_vT[base + 2048 + s + 8] = __float2half_rn(v3);
                }
            }
        }
    } else {
        const float scale = g_scales[1];
        #pragma unroll
        for (int mi = 0; mi < 4; ++mi) {
            int r = row0 + wm + mi * 16 + g;
            #pragma unroll
            for (int ni = 0; ni < 4; ++ni) {
                int c = col0 + wn + ni * 8 + tg * 2;
                float b0 = bias[c], b1 = bias[c + 1];
                *(float2*)&C[(size_t)r * N + c] =
                    make_float2(acc[mi][ni][0] * scale + b0, acc[mi][ni][1] * scale + b1);
                *(float2*)&C[(size_t)(r + 8) * N + c] =
                    make_float2(acc[mi][ni][2] * scale + b0, acc[mi][ni][3] * scale + b1);
            }
        }
    }
}

// ---------------------------------------------------------------------------
// fp16 flash attention: 3-stage cp.async K/V pipeline, ONE sync per tile.
// 128 thr / 4 warps, Bq=128 (warp w owns query cols w*32..+31), Bk=64.
// S^T = K @ Q^T, O^T = V^T @ P^T; V pre-transposed; Q pre-scaled by k2.
// ---------------------------------------------------------------------------
#define KOFFU(buf) ((buf) * (64 * 36))
#define VOFFU(buf) (3 * 64 * 36 + (buf) * (64 * 36))
#define POFFU      (6 * 64 * 36)
#define NTILES (SEQ / 64)
#define ATTN_SMEM ((6 * 64 * 36 + 128 * 36) * 4)   // 73728

__global__ __launch_bounds__(128, 2)
void attn_h(__half* __restrict__ out)
{
    extern __shared__ unsigned sma[];
    const int t    = threadIdx.x;
    const int lane = t & 31;
    const int w    = t >> 5;
    const int g    = lane >> 2;
    const int tg   = lane & 3;
    const int bh = blockIdx.y;
    const int b  = bh >> 3;
    const int h  = bh & 7;
    const int s0 = blockIdx.x * 128;
    const int wi0 = w * 32;

    const __half* qbase = g_qk + ((size_t)(b * SEQ + s0)) * 1024 + h * 64;
    const __half* kbase = g_qk + (size_t)b * SEQ * 1024 + 512 + h * 64;
    const __half* vbase = g_vT + (size_t)(b * 8 + h) * 64 * 2048;

    const unsigned sb = (unsigned)__cvta_generic_to_shared(sma);
    const int lrow = t >> 3;
    const int lch  = t & 7;

    const int arow  = (lane & 7) + ((lane >> 3) & 1) * 8;
    const int acol4 = ((lane >> 4) & 1) * 4;
    const int brow  = (lane & 7) + ((lane >> 4) & 1) * 8;
    const int bcol4 = ((lane >> 3) & 1) * 4;

    auto issueKV = [&](int buf, int j0) {
        #pragma unroll
        for (int i = 0; i < 4; ++i) {
            int row = lrow + i * 16;
            cpa16(sb + (unsigned)(KOFFU(buf) + row * 36 + lch * 4) * 4u,
                  kbase + (size_t)(j0 + row) * 1024 + lch * 8);
            cpa16(sb + (unsigned)(VOFFU(buf) + row * 36 + lch * 4) * 4u,
                  vbase + (size_t)row * 2048 + j0 + lch * 8);
        }
    };

    // prologue: group A = Q staging + KV tile 0; group B = KV tile 1
    #pragma unroll
    for (int i = 0; i < 8; ++i) {
        int row = lrow + i * 16;
        cpa16(sb + (unsigned)(POFFU + row * 36 + lch * 4) * 4u,
              qbase + (size_t)row * 1024 + lch * 8);
    }
    issueKV(0, 0);
    CP_COMMIT();
    issueKV(1, 64);
    CP_COMMIT();
    CP_WAIT1();        // group A (Q + KV0) complete
    __syncthreads();

    const unsigned* Pu = sma + POFFU;
    const unsigned sP = sb + (unsigned)POFFU * 4u;
    unsigned qf[4][4][2];
    #pragma unroll
    for (int nb = 0; nb < 4; ++nb)
        #pragma unroll
        for (int ki = 0; ki < 4; ++ki) {
            qf[nb][ki][0] = Pu[(wi0 + nb * 8 + g) * 36 + ki * 8 + tg];
            qf[nb][ki][1] = Pu[(wi0 + nb * 8 + g) * 36 + ki * 8 + tg + 4];
        }
    __half* Ph = (__half*)(sma + POFFU);

    float o[4][4][4];
    #pragma unroll
    for (int db = 0; db < 4; ++db)
        #pragma unroll
        for (int nb = 0; nb < 4; ++nb)
            #pragma unroll
            for (int r = 0; r < 4; ++r) o[db][nb][r] = 0.f;
    float l[4][2];
    #pragma unroll
    for (int nb = 0; nb < 4; ++nb) { l[nb][0] = 0.f; l[nb][1] = 0.f; }

    for (int kt = 0; kt < NTILES; ++kt) {
        if (kt > 0) {
            if (kt + 1 < NTILES) CP_WAIT1(); else CP_WAIT0();
            __syncthreads();   // tile kt visible; all warps done with tile kt-1
        }
        if (kt + 2 < NTILES) { issueKV((kt + 2) % 3, (kt + 2) * 64); CP_COMMIT(); }

        const int buf = kt % 3;
        const unsigned sK = sb + (unsigned)KOFFU(buf) * 4u;
        const unsigned sV = sb + (unsigned)VOFFU(buf) * 4u;
        const int j0 = kt * 64;
        const bool need_mask = (unsigned)(s0 + wi0 - j0 + 31) <= 101u;

        #pragma unroll
        for (int mh = 0; mh < 2; ++mh) {
            float s[2][4][4];
            #pragma unroll
            for (int mb = 0; mb < 2; ++mb)
                #pragma unroll
                for (int nb = 0; nb < 4; ++nb)
                    #pragma unroll
                    for (int r = 0; r < 4; ++r) s[mb][nb][r] = 0.f;
            #pragma unroll
            for (int ki = 0; ki < 4; ++ki) {
                unsigned af[2][4];
                #pragma unroll
                for (int mb = 0; mb < 2; ++mb)
                    ldsm4(af[mb][0], af[mb][1], af[mb][2], af[mb][3],
                          sK + (unsigned)((mh * 32 + mb * 16 + arow) * 36
                                          + ki * 8 + acol4) * 4u);
                #pragma unroll
                for (int mb = 0; mb < 2; ++mb)
                    #pragma unroll
                    for (int nb = 0; nb < 4; ++nb)
                        mma16(s[mb][nb], af[mb], qf[nb][ki]);
            }
            #pragma unroll
            for (int mb = 0; mb < 2; ++mb) {
                const int jl = mh * 32 + mb * 16 + g;
                const int jg = j0 + jl;
                #pragma unroll
                for (int nb = 0; nb < 4; ++nb) {
                    const int i0 = wi0 + nb * 8 + tg * 2;
                    float v0 = s[mb][nb][0];
                    float v1 = s[mb][nb][1];
                    float v2 = s[mb][nb][2];
                    float v3 = s[mb][nb][3];
                    if (need_mask) {
                        const int ig = s0 + i0;
                        if ((unsigned)(ig     - jg)       < 8u) v0 = -1e30f;
                        if ((unsigned)(ig + 1 - jg)       < 8u) v1 = -1e30f;
                        if ((unsigned)(ig     - (jg + 8)) < 8u) v2 = -1e30f;
                        if ((unsigned)(ig + 1 - (jg + 8)) < 8u) v3 = -1e30f;
                    }
                    float p0 = ex2f(v0);
                    float p1 = ex2f(v1);
                    float p2 = ex2f(v2);
                    float p3 = ex2f(v3);
                    l[nb][0] += p0 + p2;
                    l[nb][1] += p1 + p3;
                    Ph[(i0)     * 72 + jl]     = __float2half_rn(p0);
                    Ph[(i0 + 1) * 72 + jl]     = __float2half_rn(p1);
                    Ph[(i0)     * 72 + jl + 8] = __float2half_rn(p2);
                    Ph[(i0 + 1) * 72 + jl + 8] = __float2half_rn(p3);
                }
            }
        }
        __syncwarp();   // P stripe produced & consumed within the same warp

        #pragma unroll
        for (int kj = 0; kj < 4; ++kj) {
            unsigned pf[4][2];
            #pragma unroll
            for (int p = 0; p < 2; ++p)
                ldsm4(pf[p * 2][0], pf[p * 2][1], pf[p * 2 + 1][0], pf[p * 2 + 1][1],
                      sP + (unsigned)((wi0 + p * 16 + brow) * 36 + kj * 8 + bcol4) * 4u);
            #pragma unroll
            for (int db = 0; db < 4; ++db) {
                unsigned vf[4];
                ldsm4(vf[0], vf[1], vf[2], vf[3],
                      sV + (unsigned)((db * 16 + arow) * 36 + kj * 8 + acol4) * 4u);
                #pragma unroll
                for (int nb = 0; nb < 4; ++nb)
                    mma16(o[db][nb], vf, pf[nb]);
            }
        }
    }

    #pragma unroll
    for (int nb = 0; nb < 4; ++nb) {
        #pragma unroll
        for (int c = 0; c < 2; ++c) {
            float v = l[nb][c];
            v += __shfl_xor_sync(0xffffffffu, v, 4);
            v += __shfl_xor_sync(0xffffffffu, v, 8);
            v += __shfl_xor_sync(0xffffffffu, v, 16);
            l[nb][c] = v;
        }
    }

    __half* ob = out + ((size_t)(b * SEQ + s0 + wi0)) * INNER + h * DHEAD;
    #pragma unroll
    for (int nb = 0; nb < 4; ++nb) {
        const int i0 = nb * 8 + tg * 2;
        const float inv0 = 1.f / l[nb][0];
        const float inv1 = 1.f / l[nb][1];
        #pragma unroll
        for (int db = 0; db < 4; ++db) {
            const int d0 = db * 16 + g;
            ob[(size_t)i0 * INNER + d0]           = __float2half_rn(o[db][nb][0] * inv0);
            ob[(size_t)(i0 + 1) * INNER + d0]     = __float2half_rn(o[db][nb][1] * inv1);
            ob[(size_t)i0 * INNER + d0 + 8]       = __float2half_rn(o[db][nb][2] * inv0);
            ob[(size_t)(i0 + 1) * INNER + d0 + 8] = __float2half_rn(o[db][nb][3] * inv1);
        }
    }
}

// ---------------------------------------------------------------------------
extern "C" void kernel_launch(void* const* d_in, const int* in_sizes, int n_in,
                              void* d_out, int out_size)
{
    const float* x    = (const float*)d_in[0];
    const float* Wq   = (const float*)d_in[1];
    const float* uq   = (const float*)d_in[2];
    const float* sq   = (const float*)d_in[3];
    const float* Wo   = (const float*)d_in[4];
    const float* bo   = (const float*)d_in[5];
    const float* uo   = (const float*)d_in[6];
    const float* so   = (const float*)d_in[7];
    const float* temp = (const float*)d_in[8];

    __half* p_xh = nullptr; __half* p_wqh = nullptr; __half* p_woh = nullptr;
    __half* p_attn = nullptr;
    cudaGetSymbolAddress((void**)&p_xh,   g_xh);
    cudaGetSymbolAddress((void**)&p_wqh,  g_wqh);
    cudaGetSymbolAddress((void**)&p_woh,  g_woh);
    cudaGetSymbolAddress((void**)&p_attn, g_attn);

    prep<<<NB_CVT + 2048, 256>>>(x, Wq, Wo, uq, uo);
    sn_finish<<<32, 256>>>(Wq, Wo, sq, so, temp);

    const int smem_gemm = 3 * 2 * GST * (int)sizeof(unsigned);   // 110592
    cudaFuncSetAttribute(gemm_h, cudaFuncAttributeMaxDynamicSharedMemorySize, smem_gemm);

    // qkv projection (writes g_qk + g_vT internally)
    gemm_h<<<dim3(QKV3 / 128, MROWS / 128), 256, smem_gemm>>>(
        p_xh, p_wqh, nullptr, MROWS, QKV3, DMODEL, 0, nullptr);

    // attention
    cudaFuncSetAttribute(attn_h, cudaFuncAttributeMaxDynamicSharedMemorySize, ATTN_SMEM);
    attn_h<<<dim3(SEQ / 128, BATCH * NHEADS), 128, ATTN_SMEM>>>(p_attn);

    // out = (attn @ W_out^T) * scale_out + b_out
    gemm_h<<<dim3(DMODEL / 128, MROWS / 128), 256, smem_gemm>>>(
        p_attn, p_woh, (float*)d_out, MROWS, DMODEL, INNER, 1, bo);
}

// round 14
// speedup vs baseline: 1.0378x; 1.0378x over previous
#include <cuda_runtime.h>
#include <cuda_fp16.h>
#include <math.h>

#define BATCH 2
#define SEQ   2048
#define DMODEL 512
#define NHEADS 8
#define DHEAD 64
#define INNER 512
#define QKV3  1536
#define MROWS (BATCH*SEQ)   // 4096

// Scratch (device globals; allocation is forbidden)
__device__ __half g_qk[MROWS * 1024];            // q at [r][0..511], k at [r][512..1023]
__device__ __half g_vT[BATCH * NHEADS * DHEAD * SEQ]; // [(b*8+h)*64+d][s]
__device__ __half g_attn[MROWS * INNER];         // attention out, fp16
__device__ __half g_xh[MROWS * DMODEL];
__device__ __half g_wqh[QKV3 * DMODEL];
__device__ __half g_woh[DMODEL * INNER];
__device__ float g_t[2048];
__device__ float g_part[32];
__device__ float g_scales[2];
__device__ float g_k2q;                          // exp(temperature)*log2(e)
__device__ unsigned g_ctr = 0;                   // sn_finish completion counter

// ---------------------------------------------------------------------------
// helpers
// ---------------------------------------------------------------------------
__device__ __forceinline__ float ex2f(float x) {
    float r;
    asm("ex2.approx.ftz.f32 %0, %1;" : "=f"(r) : "f"(x));
    return r;
}

__device__ __forceinline__ void mma16(float* c, const unsigned* a, const unsigned* b) {
    asm volatile(
        "mma.sync.aligned.m16n8k16.row.col.f32.f16.f16.f32 "
        "{%0,%1,%2,%3}, {%4,%5,%6,%7}, {%8,%9}, {%0,%1,%2,%3};"
        : "+f"(c[0]), "+f"(c[1]), "+f"(c[2]), "+f"(c[3])
        : "r"(a[0]), "r"(a[1]), "r"(a[2]), "r"(a[3]), "r"(b[0]), "r"(b[1]));
}

__device__ __forceinline__ void ldsm4(unsigned& r0, unsigned& r1,
                                      unsigned& r2, unsigned& r3, unsigned a) {
    asm volatile("ldmatrix.sync.aligned.m8n8.x4.shared.b16 {%0,%1,%2,%3}, [%4];"
                 : "=r"(r0), "=r"(r1), "=r"(r2), "=r"(r3) : "r"(a));
}

__device__ __forceinline__ unsigned h2pack(float a, float b) {
    __half2 h = __floats2half2_rn(a, b);
    return *(unsigned*)&h;
}

__device__ __forceinline__ void cpa16(unsigned dst, const void* src) {
    asm volatile("cp.async.cg.shared.global [%0], [%1], 16;" :: "r"(dst), "l"(src));
}
#define CP_COMMIT() asm volatile("cp.async.commit_group;")
#define CP_WAIT0()  asm volatile("cp.async.wait_group 0;")
#define CP_WAIT1()  asm volatile("cp.async.wait_group 1;")

// ---------------------------------------------------------------------------
// prep: fused fp16 conversion (x, W_qkv, W_out) + spectral-norm row dots
// ---------------------------------------------------------------------------
#define C0 (MROWS * DMODEL / 8)
#define C1 (QKV3 * DMODEL / 8)
#define C2 (DMODEL * INNER / 8)
#define NB_CVT ((C0 + C1 + C2) / 256)
__global__ __launch_bounds__(256)
void prep(const float* __restrict__ x, const float* __restrict__ wq,
          const float* __restrict__ wo, const float* __restrict__ uq,
          const float* __restrict__ uo)
{
    const int bid = blockIdx.x;
    const int tid = threadIdx.x;
    if (bid < NB_CVT) {
        int i = bid * 256 + tid;
        const float* src; __half* dst; int off;
        if (i < C0)           { src = x;  dst = g_xh;  off = i; }
        else if (i < C0 + C1) { src = wq; dst = g_wqh; off = i - C0; }
        else                  { src = wo; dst = g_woh; off = i - C0 - C1; }
        float4 a = ((const float4*)src)[(size_t)off * 2];
        float4 b = ((const float4*)src)[(size_t)off * 2 + 1];
        __half2 h0 = __floats2half2_rn(a.x, a.y);
        __half2 h1 = __floats2half2_rn(a.z, a.w);
        __half2 h2 = __floats2half2_rn(b.x, b.y);
        __half2 h3 = __floats2half2_rn(b.z, b.w);
        uint4 u = make_uint4(*(unsigned*)&h0, *(unsigned*)&h1,
                             *(unsigned*)&h2, *(unsigned*)&h3);
        *(uint4*)(dst + (size_t)off * 8) = u;
    } else {
        int rb = bid - NB_CVT;
        const float* W; const float* u; int row;
        if (rb < 1536) { W = wq; u = uq; row = rb; }
        else           { W = wo; u = uo; row = rb - 1536; }
        const float* wr = W + (size_t)row * 512;
        float s = wr[tid] * u[tid] + wr[tid + 256] * u[tid + 256];
        #pragma unroll
        for (int o = 16; o >= 1; o >>= 1) s += __shfl_xor_sync(0xffffffffu, s, o);
        __shared__ float red[8];
        if ((tid & 31) == 0) red[tid >> 5] = s;
        __syncthreads();
        if (tid == 0) {
            float tot = 0.f;
            #pragma unroll
            for (int q = 0; q < 8; ++q) tot += red[q];
            g_t[rb] = tot;
        }
    }
}

// ---------------------------------------------------------------------------
// sn_finish: coldot partials (32 blocks); last block computes both scales.
// ---------------------------------------------------------------------------
__global__ __launch_bounds__(256)
void sn_finish(const float* __restrict__ Wq, const float* __restrict__ Wo,
               const float* __restrict__ sq, const float* __restrict__ so,
               const float* __restrict__ temp)
{
    const int blk = blockIdx.x;
    const int tid = threadIdx.x;
    {
        int w = blk >> 4;
        int cblk = blk & 15;
        const float* W = w ? Wo : Wq;
        int R = w ? 512 : 1536;
        int toff = w ? 1536 : 0;
        int dl = tid & 31;
        int rg = tid >> 5;
        int d = cblk * 32 + dl;
        float s = 0.f;
        for (int r = rg; r < R; r += 8) s += W[(size_t)r * 512 + d] * g_t[toff + r];
        __shared__ float red[8][33];
        red[rg][dl] = s;
        __syncthreads();
        if (rg == 0) {
            float cs = 0.f;
            #pragma unroll
            for (int q = 0; q < 8; ++q) cs += red[q][dl];
            cs = cs * cs;
            #pragma unroll
            for (int o = 16; o >= 1; o >>= 1) cs += __shfl_xor_sync(0xffffffffu, cs, o);
            if (dl == 0) g_part[blk] = cs;
        }
    }
    __threadfence();
    __syncthreads();
    __shared__ unsigned last;
    if (tid == 0) last = atomicAdd(&g_ctr, 1u);
    __syncthreads();
    if (last != 31) return;
    __threadfence();

    const int w  = tid >> 7;
    const int tl = tid & 127;
    float ssq = (tl < 16) ? g_part[w * 16 + tl] : 0.f;
    const int R = w ? 512 : 1536;
    const int off = w ? 1536 : 0;
    float tt = 0.f;
    for (int r = tl; r < R; r += 128) { float v = g_t[off + r]; tt += v * v; }
    __shared__ float ra[256], rb[256];
    ra[tid] = ssq; rb[tid] = tt;
    __syncthreads();
    for (int sft = 64; sft >= 1; sft >>= 1) {
        if (tl < sft) { ra[tid] += ra[tid + sft]; rb[tid] += rb[tid + sft]; }
        __syncthreads();
    }
    if (tl == 0) {
        float sigma_w = sqrtf(ra[w * 128] / rb[w * 128]);
        g_scales[w] = (w ? so[0] : sq[0]) / sigma_w;
        if (w == 0) {
            g_k2q = expf(temp[0]) * 1.4426950408889634f;
            g_ctr = 0;
        }
    }
}

// ---------------------------------------------------------------------------
// fp16 GEMM with ldmatrix fragment loads (round-10/11 validated).
// ---------------------------------------------------------------------------
#define GST (128 * 36)
__global__ __launch_bounds__(256, 2)
void gemm_h(const __half* __restrict__ A, const __half* __restrict__ B,
            float* __restrict__ C, int M, int N, int K,
            int mode, const float* __restrict__ bias)
{
    extern __shared__ unsigned smg[];
    const int t    = threadIdx.x;
    const int lane = t & 31;
    const int wid  = t >> 5;
    const int g  = lane >> 2;
    const int tg = lane & 3;
    const int wm = (wid >> 2) * 64;
    const int wn = (wid & 3) * 32;
    const int row0 = blockIdx.y * 128;
    const int col0 = blockIdx.x * 128;
    const int NK = K >> 6;

    const unsigned sb = (unsigned)__cvta_generic_to_shared(smg);
    const int crow = t >> 3;
    const int cch  = (t & 7) * 8;

    const int arow  = (lane & 7) + ((lane >> 3) & 1) * 8;
    const int acol4 = ((lane >> 4) & 1) * 4;
    const int brow  = (lane & 7) + ((lane >> 4) & 1) * 8;
    const int bcol4 = ((lane >> 3) & 1) * 4;

    auto issue = [&](int st, int k0) {
        unsigned so = sb + (unsigned)(st * 2 * GST) * 4u;
        #pragma unroll
        for (int i = 0; i < 4; ++i) {
            int row = crow + i * 32;
            cpa16(so + (unsigned)(row * 36 + (t & 7) * 4) * 4u,
                  A + (size_t)(row0 + row) * K + k0 + cch);
            cpa16(so + (unsigned)(GST + row * 36 + (t & 7) * 4) * 4u,
                  B + (size_t)(col0 + row) * K + k0 + cch);
        }
    };

    issue(0, 0);  CP_COMMIT();
    issue(1, 64); CP_COMMIT();

    float acc[4][4][4];
    #pragma unroll
    for (int mi = 0; mi < 4; ++mi)
        #pragma unroll
        for (int ni = 0; ni < 4; ++ni)
            #pragma unroll
            for (int r = 0; r < 4; ++r) acc[mi][ni][r] = 0.f;

    for (int ks = 0; ks < NK; ++ks) {
        if (ks + 1 < NK) CP_WAIT1(); else CP_WAIT0();
        __syncthreads();
        if (ks + 2 < NK) { issue((ks + 2) % 3, (ks + 2) * 64); CP_COMMIT(); }

        const unsigned sA = sb + (unsigned)((ks % 3) * 2 * GST) * 4u;
        const unsigned sB = sA + (unsigned)GST * 4u;
        #pragma unroll
        for (int ki = 0; ki < 4; ++ki) {
            const int kk = ki * 8;
            unsigned af[4][4], bf[4][2];
            #pragma unroll
            for (int mi = 0; mi < 4; ++mi)
                ldsm4(af[mi][0], af[mi][1], af[mi][2], af[mi][3],
                      sA + (unsigned)((wm + mi * 16 + arow) * 36 + kk + acol4) * 4u);
            #pragma unroll
            for (int p = 0; p < 2; ++p)
                ldsm4(bf[p * 2][0], bf[p * 2][1], bf[p * 2 + 1][0], bf[p * 2 + 1][1],
                      sB + (unsigned)((wn + p * 16 + brow) * 36 + kk + bcol4) * 4u);
            #pragma unroll
            for (int mi = 0; mi < 4; ++mi)
                #pragma unroll
                for (int ni = 0; ni < 4; ++ni)
                    mma16(acc[mi][ni], af[mi], bf[ni]);
        }
    }

    if (mode == 0) {
        float scale = g_scales[0];
        if (col0 < 512) scale *= g_k2q;
        const bool is_v = (col0 >= 1024);
        #pragma unroll
        for (int mi = 0; mi < 4; ++mi) {
            int r = row0 + wm + mi * 16 + g;
            #pragma unroll
            for (int ni = 0; ni < 4; ++ni) {
                int c = col0 + wn + ni * 8 + tg * 2;
                float v0 = acc[mi][ni][0] * scale;
                float v1 = acc[mi][ni][1] * scale;
                float v2 = acc[mi][ni][2] * scale;
                float v3 = acc[mi][ni][3] * scale;
                if (!is_v) {
                    __half2 lo = __floats2half2_rn(v0, v1);
                    __half2 hi = __floats2half2_rn(v2, v3);
                    *(__half2*)&g_qk[(size_t)r * 1024 + c]       = lo;
                    *(__half2*)&g_qk[(size_t)(r + 8) * 1024 + c] = hi;
                } else {
                    int cd = c - 1024;
                    int h  = cd >> 6;
                    int d  = cd & 63;
                    int b  = r >> 11;
                    int s  = r & 2047;
                    size_t base = ((size_t)(b * 8 + h) * 64 + d) * 2048;
                    g_vT[base + s]            = __float2half_rn(v0);
                    g_vT[base + 2048 + s]     = __float2half_rn(v1);
                    g_vT[base + s + 8]        = __float2half_rn(v2);
                    g_vT[base + 2048 + s + 8] = __float2half_rn(v3);
                }
            }
        }
    } else {
        const float scale = g_scales[1];
        #pragma unroll
        for (int mi = 0; mi < 4; ++mi) {
            int r = row0 + wm + mi * 16 + g;
            #pragma unroll
            for (int ni = 0; ni < 4; ++ni) {
                int c = col0 + wn + ni * 8 + tg * 2;
                float b0 = bias[c], b1 = bias[c + 1];
                *(float2*)&C[(size_t)r * N + c] =
                    make_float2(acc[mi][ni][0] * scale + b0, acc[mi][ni][1] * scale + b1);
                *(float2*)&C[(size_t)(r + 8) * N + c] =
                    make_float2(acc[mi][ni][2] * scale + b0, acc[mi][ni][3] * scale + b1);
            }
        }
    }
}

// ---------------------------------------------------------------------------
// fp16 flash attention, FA2 register-resident P (no P smem round-trip).
// 128 thr / 4 warps, Bq=128 (warp w owns q ROWS w*32..+31), Bk=64.
// S = Q@K^T (A=Q[i][d], B=K[j][d]); P packed in regs as A-operand;
// O = P@V (B=V^T[d][j] from g_vT). 3-stage cp.async pipeline.
// ---------------------------------------------------------------------------
#define KOFFU(buf) ((buf) * (64 * 36))
#define VOFFU(buf) (3 * 64 * 36 + (buf) * (64 * 36))
#define QOFFU      (6 * 64 * 36)
#define NTILES (SEQ / 64)
#define ATTN_SMEM ((6 * 64 * 36 + 128 * 36) * 4)   // 73728

__global__ __launch_bounds__(128, 2)
void attn_h(__half* __restrict__ out)
{
    extern __shared__ unsigned sma[];
    const int t    = threadIdx.x;
    const int lane = t & 31;
    const int w    = t >> 5;
    const int g    = lane >> 2;
    const int tg   = lane & 3;
    const int bh = blockIdx.y;
    const int b  = bh >> 3;
    const int h  = bh & 7;
    const int s0 = blockIdx.x * 128;
    const int wi0 = w * 32;

    const __half* qbase = g_qk + ((size_t)(b * SEQ + s0)) * 1024 + h * 64;
    const __half* kbase = g_qk + (size_t)b * SEQ * 1024 + 512 + h * 64;
    const __half* vbase = g_vT + (size_t)(b * 8 + h) * 64 * 2048;

    const unsigned sb = (unsigned)__cvta_generic_to_shared(sma);
    const int lrow = t >> 3;
    const int lch  = t & 7;

    const int arow  = (lane & 7) + ((lane >> 3) & 1) * 8;
    const int acol4 = ((lane >> 4) & 1) * 4;
    const int brow  = (lane & 7) + ((lane >> 4) & 1) * 8;
    const int bcol4 = ((lane >> 3) & 1) * 4;

    auto issueKV = [&](int buf, int j0) {
        #pragma unroll
        for (int i = 0; i < 4; ++i) {
            int row = lrow + i * 16;
            cpa16(sb + (unsigned)(KOFFU(buf) + row * 36 + lch * 4) * 4u,
                  kbase + (size_t)(j0 + row) * 1024 + lch * 8);
            cpa16(sb + (unsigned)(VOFFU(buf) + row * 36 + lch * 4) * 4u,
                  vbase + (size_t)row * 2048 + j0 + lch * 8);
        }
    };

    // prologue: group A = Q staging + KV tile 0; group B = KV tile 1
    #pragma unroll
    for (int i = 0; i < 8; ++i) {
        int row = lrow + i * 16;
        cpa16(sb + (unsigned)(QOFFU + row * 36 + lch * 4) * 4u,
              qbase + (size_t)row * 1024 + lch * 8);
    }
    issueKV(0, 0);
    CP_COMMIT();
    issueKV(1, 64);
    CP_COMMIT();
    CP_WAIT1();
    __syncthreads();

    // Q fragments (A-operand): qf[mb][ki][4]
    const unsigned sQ = sb + (unsigned)QOFFU * 4u;
    unsigned qf[2][4][4];
    #pragma unroll
    for (int mb = 0; mb < 2; ++mb)
        #pragma unroll
        for (int ki = 0; ki < 4; ++ki)
            ldsm4(qf[mb][ki][0], qf[mb][ki][1], qf[mb][ki][2], qf[mb][ki][3],
                  sQ + (unsigned)((wi0 + mb * 16 + arow) * 36 + ki * 8 + acol4) * 4u);

    float o[2][8][4];
    #pragma unroll
    for (int mb = 0; mb < 2; ++mb)
        #pragma unroll
        for (int nd = 0; nd < 8; ++nd)
            #pragma unroll
            for (int r = 0; r < 4; ++r) o[mb][nd][r] = 0.f;
    float l[2][2];
    l[0][0] = l[0][1] = l[1][0] = l[1][1] = 0.f;

    for (int kt = 0; kt < NTILES; ++kt) {
        if (kt > 0) {
            if (kt + 1 < NTILES) CP_WAIT1(); else CP_WAIT0();
            __syncthreads();
        }
        if (kt + 2 < NTILES) { issueKV((kt + 2) % 3, (kt + 2) * 64); CP_COMMIT(); }

        const int buf = kt % 3;
        const unsigned sK = sb + (unsigned)KOFFU(buf) * 4u;
        const unsigned sV = sb + (unsigned)VOFFU(buf) * 4u;
        const int j0 = kt * 64;
        const bool need_mask = (unsigned)(s0 + wi0 - j0 + 31) <= 101u;

        unsigned pa[2][4][4];   // P as A-operand fragments, [mb][kj-block][4]

        #pragma unroll
        for (int nh = 0; nh < 2; ++nh) {   // j half (32 wide)
            float s[2][4][4];
            #pragma unroll
            for (int mb = 0; mb < 2; ++mb)
                #pragma unroll
                for (int nb = 0; nb < 4; ++nb)
                    #pragma unroll
                    for (int r = 0; r < 4; ++r) s[mb][nb][r] = 0.f;
            #pragma unroll
            for (int ki = 0; ki < 4; ++ki) {
                unsigned bf[4][2];
                #pragma unroll
                for (int p = 0; p < 2; ++p)
                    ldsm4(bf[p * 2][0], bf[p * 2][1], bf[p * 2 + 1][0], bf[p * 2 + 1][1],
                          sK + (unsigned)((nh * 32 + p * 16 + brow) * 36
                                          + ki * 8 + bcol4) * 4u);
                #pragma unroll
                for (int mb = 0; mb < 2; ++mb)
                    #pragma unroll
                    for (int nb = 0; nb < 4; ++nb)
                        mma16(s[mb][nb], qf[mb][ki], bf[nb]);
            }
            // softmax (no-max; logits bounded) + pack to A-operand fragments
            #pragma unroll
            for (int mb = 0; mb < 2; ++mb) {
                const int ig = s0 + wi0 + mb * 16 + g;
                #pragma unroll
                for (int nbp = 0; nbp < 2; ++nbp) {
                    float p[2][4];
                    #pragma unroll
                    for (int q2 = 0; q2 < 2; ++q2) {
                        const int nb = nbp * 2 + q2;
                        const int jg = j0 + nh * 32 + nb * 8 + tg * 2;
                        float v0 = s[mb][nb][0];
                        float v1 = s[mb][nb][1];
                        float v2 = s[mb][nb][2];
                        float v3 = s[mb][nb][3];
                        if (need_mask) {
                            if ((unsigned)(ig     - jg)       < 8u) v0 = -1e30f;
                            if ((unsigned)(ig     - (jg + 1)) < 8u) v1 = -1e30f;
                            if ((unsigned)(ig + 8 - jg)       < 8u) v2 = -1e30f;
                            if ((unsigned)(ig + 7 - jg)       < 8u) v3 = -1e30f;
                        }
                        p[q2][0] = ex2f(v0);
                        p[q2][1] = ex2f(v1);
                        p[q2][2] = ex2f(v2);
                        p[q2][3] = ex2f(v3);
                        l[mb][0] += p[q2][0] + p[q2][1];
                        l[mb][1] += p[q2][2] + p[q2][3];
                    }
                    const int q = nh * 2 + nbp;
                    pa[mb][q][0] = h2pack(p[0][0], p[0][1]);
                    pa[mb][q][1] = h2pack(p[0][2], p[0][3]);
                    pa[mb][q][2] = h2pack(p[1][0], p[1][1]);
                    pa[mb][q][3] = h2pack(p[1][2], p[1][3]);
                }
            }
        }

        // O += P @ V  (B = V^T stored [d][j])
        #pragma unroll
        for (int q = 0; q < 4; ++q) {
            unsigned vf[8][2];
            #pragma unroll
            for (int np = 0; np < 4; ++np)
                ldsm4(vf[np * 2][0], vf[np * 2][1], vf[np * 2 + 1][0], vf[np * 2 + 1][1],
                      sV + (unsigned)((np * 16 + brow) * 36 + q * 8 + bcol4) * 4u);
            #pragma unroll
            for (int mb = 0; mb < 2; ++mb)
                #pragma unroll
                for (int nd = 0; nd < 8; ++nd)
                    mma16(o[mb][nd], pa[mb][q], vf[nd]);
        }
    }

    // reduce row sums over the 4 lanes sharing g (xor 1, 2)
    #pragma unroll
    for (int mb = 0; mb < 2; ++mb)
        #pragma unroll
        for (int c = 0; c < 2; ++c) {
            float v = l[mb][c];
            v += __shfl_xor_sync(0xffffffffu, v, 1);
            v += __shfl_xor_sync(0xffffffffu, v, 2);
            l[mb][c] = v;
        }

    // epilogue: out[b][s0+wi0+row][h*64+d] = O / l  (direct row-major half2)
    __half* ob = out + ((size_t)(b * SEQ + s0 + wi0)) * INNER + h * DHEAD;
    #pragma unroll
    for (int mb = 0; mb < 2; ++mb) {
        const float invg  = 1.f / l[mb][0];
        const float invg8 = 1.f / l[mb][1];
        const int r0 = mb * 16 + g;
        #pragma unroll
        for (int nd = 0; nd < 8; ++nd) {
            const int d = nd * 8 + tg * 2;
            *(__half2*)&ob[(size_t)r0 * INNER + d] =
                __floats2half2_rn(o[mb][nd][0] * invg, o[mb][nd][1] * invg);
            *(__half2*)&ob[(size_t)(r0 + 8) * INNER + d] =
                __floats2half2_rn(o[mb][nd][2] * invg8, o[mb][nd][3] * invg8);
        }
    }
}

// ---------------------------------------------------------------------------
extern "C" void kernel_launch(void* const* d_in, const int* in_sizes, int n_in,
                              void* d_out, int out_size)
{
    const float* x    = (const float*)d_in[0];
    const float* Wq   = (const float*)d_in[1];
    const float* uq   = (const float*)d_in[2];
    const float* sq   = (const float*)d_in[3];
    const float* Wo   = (const float*)d_in[4];
    const float* bo   = (const float*)d_in[5];
    const float* uo   = (const float*)d_in[6];
    const float* so   = (const float*)d_in[7];
    const float* temp = (const float*)d_in[8];

    __half* p_xh = nullptr; __half* p_wqh = nullptr; __half* p_woh = nullptr;
    __half* p_attn = nullptr;
    cudaGetSymbolAddress((void**)&p_xh,   g_xh);
    cudaGetSymbolAddress((void**)&p_wqh,  g_wqh);
    cudaGetSymbolAddress((void**)&p_woh,  g_woh);
    cudaGetSymbolAddress((void**)&p_attn, g_attn);

    prep<<<NB_CVT + 2048, 256>>>(x, Wq, Wo, uq, uo);
    sn_finish<<<32, 256>>>(Wq, Wo, sq, so, temp);

    const int smem_gemm = 3 * 2 * GST * (int)sizeof(unsigned);   // 110592
    cudaFuncSetAttribute(gemm_h, cudaFuncAttributeMaxDynamicSharedMemorySize, smem_gemm);

    // qkv projection (writes g_qk + g_vT internally)
    gemm_h<<<dim3(QKV3 / 128, MROWS / 128), 256, smem_gemm>>>(
        p_xh, p_wqh, nullptr, MROWS, QKV3, DMODEL, 0, nullptr);

    // attention
    cudaFuncSetAttribute(attn_h, cudaFuncAttributeMaxDynamicSharedMemorySize, ATTN_SMEM);
    attn_h<<<dim3(SEQ / 128, BATCH * NHEADS), 128, ATTN_SMEM>>>(p_attn);

    // out = (attn @ W_out^T) * scale_out + b_out
    gemm_h<<<dim3(DMODEL / 128, MROWS / 128), 256, smem_gemm>>>(
        p_attn, p_woh, (float*)d_out, MROWS, DMODEL, INNER, 1, bo);
}